// round 1
// baseline (speedup 1.0000x reference)
#include <cuda_runtime.h>
#include <cuda_bf16.h>

#define NN 8192

// Scratch (no device allocation allowed in kernel_launch)
__device__ int d_parent[NN];
__device__ unsigned int d_poscount;

__global__ void hc_init_kernel() {
    int i = blockIdx.x * blockDim.x + threadIdx.x;
    if (i < NN) d_parent[i] = i;
    if (i == 0) d_poscount = 0u;
}

// Lock-free union-find: find with path halving (benign races — writes always
// point to an ancestor), union by smaller-index root via atomicCAS hooking.
__device__ __forceinline__ int uf_find(int x) {
    while (true) {
        int p = d_parent[x];
        if (p == x) return x;
        int gp = d_parent[p];
        if (gp == p) return p;
        d_parent[x] = gp;   // path halving
        x = gp;
    }
}

__device__ __forceinline__ void uf_union(int a, int b) {
    while (true) {
        a = uf_find(a);
        b = uf_find(b);
        if (a == b) return;
        int lo = min(a, b);
        int hi = max(a, b);
        int old = atomicCAS(&d_parent[hi], hi, lo);
        if (old == hi) return;
        a = lo;
        b = old;   // hi got hooked elsewhere meanwhile; retry with its new parent
    }
}

// Stream the full 256MB matrix once: count positives (full matrix, diagonal
// included, to match the reference's sum(adj>0)//2), and union upper-triangle
// edges into the parent forest.
__global__ void hc_scan_kernel(const float4* __restrict__ adj4) {
    const int total4 = NN * (NN / 4);          // 16,777,216 float4
    int tid = blockIdx.x * blockDim.x + threadIdx.x;
    int stride = gridDim.x * blockDim.x;

    unsigned int cnt = 0;
    for (int idx = tid; idx < total4; idx += stride) {
        float4 v = adj4[idx];
        int row  = idx >> 11;                  // 2048 float4 per row
        int col0 = (idx & 2047) << 2;

        cnt += (v.x > 0.0f) ? 1u : 0u;
        cnt += (v.y > 0.0f) ? 1u : 0u;
        cnt += (v.z > 0.0f) ? 1u : 0u;
        cnt += (v.w > 0.0f) ? 1u : 0u;

        // union only strictly-upper entries (symmetric matrix; self-loops
        // don't affect connectivity)
        if (col0 + 3 > row) {   // quick reject for fully lower-triangle quads
            if (v.x > 0.0f && col0 + 0 > row) uf_union(row, col0 + 0);
            if (v.y > 0.0f && col0 + 1 > row) uf_union(row, col0 + 1);
            if (v.z > 0.0f && col0 + 2 > row) uf_union(row, col0 + 2);
            if (v.w > 0.0f && col0 + 3 > row) uf_union(row, col0 + 3);
        }
    }

    // block reduction -> 1 atomicAdd per block
    __shared__ unsigned int sh[256];
    int t = threadIdx.x;
    sh[t] = cnt;
    __syncthreads();
    for (int s = 128; s > 0; s >>= 1) {
        if (t < s) sh[t] += sh[t + s];
        __syncthreads();
    }
    if (t == 0) atomicAdd(&d_poscount, sh[0]);
}

__global__ void hc_finish_kernel(float* __restrict__ out) {
    __shared__ int sh[256];
    int t = threadIdx.x;
    int roots = 0;
    for (int i = t; i < NN; i += 256)
        roots += (d_parent[i] == i) ? 1 : 0;
    sh[t] = roots;
    __syncthreads();
    for (int s = 128; s > 0; s >>= 1) {
        if (t < s) sh[t] += sh[t + s];
        __syncthreads();
    }
    if (t == 0) {
        float n_comp  = (float)sh[0];
        float n_edges = (float)(d_poscount / 2u);   // integer //2, matches ref
        float betti1  = n_edges - (float)NN + n_comp;
        float n_cyc   = fmaxf(0.0f, betti1);
        float comp_l  = (n_comp - 1.0f) * (n_comp - 1.0f);
        out[0] = comp_l + n_cyc * n_cyc;
    }
}

extern "C" void kernel_launch(void* const* d_in, const int* in_sizes, int n_in,
                              void* d_out, int out_size) {
    const float4* adj4 = (const float4*)d_in[0];
    float* out = (float*)d_out;

    hc_init_kernel<<<(NN + 255) / 256, 256>>>();
    hc_scan_kernel<<<2048, 256>>>(adj4);
    hc_finish_kernel<<<1, 256>>>(out);
}

// round 2
// speedup vs baseline: 1.8487x; 1.8487x over previous
#include <cuda_runtime.h>
#include <cuda_bf16.h>

#define NN 8192

// Scratch (no device allocation allowed anywhere)
__device__ int d_parent[NN];
__device__ unsigned int d_ucount;   // strictly-upper positives
__device__ unsigned int d_dcount;   // diagonal positives

__global__ void hc_init_kernel() {
    int i = blockIdx.x * blockDim.x + threadIdx.x;
    if (i < NN) d_parent[i] = i;
    if (i == 0) { d_ucount = 0u; d_dcount = 0u; }
}

// Lock-free union-find: find with path halving (benign races — writes always
// point to an ancestor), union by smaller-index root via atomicCAS hooking.
// __noinline__ keeps the rare union path out of the hot streaming loop so
// ptxas can pipeline the loads.
__device__ __noinline__ void uf_union(int a, int b) {
    while (true) {
        // find(a)
        while (true) {
            int p = d_parent[a];
            if (p == a) break;
            int gp = d_parent[p];
            if (gp == p) { a = p; break; }
            d_parent[a] = gp; a = gp;
        }
        // find(b)
        while (true) {
            int p = d_parent[b];
            if (p == b) break;
            int gp = d_parent[p];
            if (gp == p) { b = p; break; }
            d_parent[b] = gp; b = gp;
        }
        if (a == b) return;
        int lo = min(a, b);
        int hi = max(a, b);
        int old = atomicCAS(&d_parent[hi], hi, lo);
        if (old == hi) return;
        a = lo;
        b = old;   // hi got hooked meanwhile; retry against its new parent
    }
}

// Upper-triangle-only scan. Block b handles the row pair (b, NN-1-b):
// upper part of row i has NN-i elements, so each pair covers exactly NN+1
// elements -> perfect load balance. Counts strictly-upper (U) and diagonal
// (D) positives; unions strictly-upper edges.
// Exactness: adj is bitwise symmetric, so full-matrix positive count
// = 2U + D, and reference n_edges = (2U+D)//2 = U + D//2.
__global__ void hc_scan_upper(const float* __restrict__ adj) {
    const int pair = blockIdx.x;             // 0..NN/2-1
    const int t = threadIdx.x;
    unsigned int u_cnt = 0, d_cnt = 0;

    #pragma unroll
    for (int half = 0; half < 2; half++) {
        const int row = (half == 0) ? pair : (NN - 1 - pair);
        const float4* __restrict__ rowp =
            (const float4*)(adj + (size_t)row * NN);
        const int start4 = row >> 2;         // quad containing the diagonal

        for (int idx4 = start4 + t; idx4 < NN / 4; idx4 += 256) {
            float4 v = __ldcs(&rowp[idx4]);
            int col0 = idx4 << 2;

            bool p0 = v.x > 0.0f, p1 = v.y > 0.0f,
                 p2 = v.z > 0.0f, p3 = v.w > 0.0f;
            bool up0 = p0 && (col0 + 0 > row);
            bool up1 = p1 && (col0 + 1 > row);
            bool up2 = p2 && (col0 + 2 > row);
            bool up3 = p3 && (col0 + 3 > row);

            u_cnt += (unsigned)up0 + (unsigned)up1 +
                     (unsigned)up2 + (unsigned)up3;
            // diagonal lives only in the first quad of the row
            if (idx4 == start4) {
                d_cnt += (unsigned)(p0 && (col0 + 0 == row));
                d_cnt += (unsigned)(p1 && (col0 + 1 == row));
                d_cnt += (unsigned)(p2 && (col0 + 2 == row));
                d_cnt += (unsigned)(p3 && (col0 + 3 == row));
            }

            if (up0 | up1 | up2 | up3) {     // rare (~0.23% density)
                if (up0) uf_union(row, col0 + 0);
                if (up1) uf_union(row, col0 + 1);
                if (up2) uf_union(row, col0 + 2);
                if (up3) uf_union(row, col0 + 3);
            }
        }
    }

    // warp reduce, then block reduce -> 2 atomics per block
    for (int s = 16; s > 0; s >>= 1) {
        u_cnt += __shfl_down_sync(0xFFFFFFFFu, u_cnt, s);
        d_cnt += __shfl_down_sync(0xFFFFFFFFu, d_cnt, s);
    }
    __shared__ unsigned int shu[8], shd[8];
    int lane = t & 31, w = t >> 5;
    if (lane == 0) { shu[w] = u_cnt; shd[w] = d_cnt; }
    __syncthreads();
    if (t == 0) {
        unsigned int su = 0, sd = 0;
        #pragma unroll
        for (int i = 0; i < 8; i++) { su += shu[i]; sd += shd[i]; }
        atomicAdd(&d_ucount, su);
        atomicAdd(&d_dcount, sd);
    }
}

__global__ void hc_finish_kernel(float* __restrict__ out) {
    __shared__ int sh[256];
    int t = threadIdx.x;
    int roots = 0;
    for (int i = t; i < NN; i += 256)
        roots += (d_parent[i] == i) ? 1 : 0;
    sh[t] = roots;
    __syncthreads();
    for (int s = 128; s > 0; s >>= 1) {
        if (t < s) sh[t] += sh[t + s];
        __syncthreads();
    }
    if (t == 0) {
        float n_comp  = (float)sh[0];
        unsigned int total_half = d_ucount + (d_dcount >> 1);  // (2U+D)//2
        float n_edges = (float)total_half;
        float betti1  = n_edges - (float)NN + n_comp;
        float n_cyc   = fmaxf(0.0f, betti1);
        float comp_l  = (n_comp - 1.0f) * (n_comp - 1.0f);
        out[0] = comp_l + n_cyc * n_cyc;
    }
}

extern "C" void kernel_launch(void* const* d_in, const int* in_sizes, int n_in,
                              void* d_out, int out_size) {
    const float* adj = (const float*)d_in[0];
    float* out = (float*)d_out;

    hc_init_kernel<<<(NN + 255) / 256, 256>>>();
    hc_scan_upper<<<NN / 2, 256>>>(adj);
    hc_finish_kernel<<<1, 256>>>(out);
}